// round 14
// baseline (speedup 1.0000x reference)
#include <cuda_runtime.h>
#include <cuda_fp16.h>
#include <cstdint>
#include <cstddef>

#define NNODES 65536
#define NDIR   9
#define NTILES (NNODES / 64)         // 1024 tiles of 64 nodes
#define NBUCK  (NTILES * NDIR)       // 9216
#define EMAX   1048576
#define NW     (NDIR * 128 * 128)

// ---------------- scratch (static device globals; no allocation) ----------------
__device__ __align__(256) float g_acc[(size_t)NNODES * 128];
__device__ __align__(256) float g_acc3[(size_t)NNODES * 128];
__device__ __align__(256) __half g_Abx[(size_t)NNODES * 128]; // fp16 features
__device__ __align__(256) __half g_Abh[(size_t)NNODES * 128];
__device__ __align__(256) __half g_WbA[(size_t)(NDIR + 1) * 128 * 128]; // W1 dirs 0-8, W3 as dir 9
__device__ __align__(256) __half g_Wb2[(size_t)NW];
__device__ __align__(16) int g_cnt[NBUCK];
__device__ __align__(16) int g_boffs[NBUCK + 4];
__device__ __align__(16) int g_cur[NBUCK];
__device__ int g_part[16];
__device__ uint32_t g_ebuf[EMAX];    // packed: dst[0:16) | localsrc[16:22)

// ---------------- PTX helpers ----------------
__device__ __forceinline__ uint32_t smem_u32(const void* p) {
    uint32_t a;
    asm("{ .reg .u64 t; cvta.to.shared.u64 t, %1; cvt.u32.u64 %0, t; }" : "=r"(a) : "l"(p));
    return a;
}
__device__ __forceinline__ void cp_async16(uint32_t saddr, const void* gptr) {
    asm volatile("cp.async.cg.shared.global [%0], [%1], 16;" :: "r"(saddr), "l"(gptr) : "memory");
}
__device__ __forceinline__ void cp_commit() {
    asm volatile("cp.async.commit_group;" ::: "memory");
}
template <int N>
__device__ __forceinline__ void cp_wait() {
    asm volatile("cp.async.wait_group %0;" :: "n"(N) : "memory");
}
__device__ __forceinline__ void ldsm_x4(uint32_t* r, uint32_t addr) {
    asm volatile("ldmatrix.sync.aligned.m8n8.x4.shared.b16 {%0,%1,%2,%3}, [%4];"
                 : "=r"(r[0]), "=r"(r[1]), "=r"(r[2]), "=r"(r[3]) : "r"(addr));
}
__device__ __forceinline__ void mma16816(float* d, const uint32_t* a, const uint32_t* b) {
    asm volatile(
        "mma.sync.aligned.m16n8k16.row.col.f32.f16.f16.f32 "
        "{%0,%1,%2,%3}, {%4,%5,%6,%7}, {%8,%9}, {%0,%1,%2,%3};"
        : "+f"(d[0]), "+f"(d[1]), "+f"(d[2]), "+f"(d[3])
        : "r"(a[0]), "r"(a[1]), "r"(a[2]), "r"(a[3]), "r"(b[0]), "r"(b[1]));
}
__device__ __forceinline__ float elu1(float t) { return t > 0.f ? t : expm1f(t); }

// SMEM layout (dynamic, 1024-aligned base):
//   [0, 8K)   A chunk0 | [8K,16K) A chunk1 | [16K,32K) B chunk0 | [32K,48K) B chunk1
//   after mainloop, region reused as Y tile: float[64][128] (32KB, 512B rows
//   — contiguous for cp.reduce.async.bulk source)
static constexpr int YSTRIDE = 128;
static constexpr int SMEM_BYTES = 1024 + 49152;   // 50176 -> 4 CTAs/SM

// ---------------- fused GEMM + TMA-reduce scatter ----------------
// grid = (ndirs, 1024). CTA computes Y tile [64 nodes x 128 cols] for weight block
// blockIdx.x (K=128 fp16), then issues one cp.reduce.async.bulk per bucket edge:
// 512B fp32 add-reduce from the SMEM Y row into the accumulator row. The TMA/L2
// performs the RMW asynchronously; SM issue cost per edge is ~1 instruction.
// WITH_SC: blockIdx.x == NDIR means shortcut (W3): bucket dir 0, target acc3.
template <bool WITH_SC>
__global__ void __launch_bounds__(128, 4)
gemm_scatter_kernel(const __half* __restrict__ Ab,   // [N][128] fp16
                    const __half* __restrict__ Bb,   // [(ndirs)*128][128] fp16, k contiguous
                    const int* __restrict__ boffs,
                    const uint32_t* __restrict__ ebuf,
                    float* __restrict__ gacc,
                    float* __restrict__ gacc3)
{
    extern __shared__ char smem_raw[];
    char* sdata = (char*)(((uintptr_t)smem_raw + 1023) & ~(uintptr_t)1023);
    const uint32_t sb = smem_u32(sdata);

    const int tid = threadIdx.x;
    const int wid = tid >> 5, lane = tid & 31;
    const int warpM = wid & 1;        // 2 warps over M (32 rows each)
    const int warpN = wid >> 1;       // 2 warps over N (64 cols each)
    const int rowBase = blockIdx.y << 6;
    const int colBase = blockIdx.x << 7;   // weight row block
    const bool sc = WITH_SC && (blockIdx.x == NDIR);
    const int bdir = sc ? 0 : blockIdx.x;
    const int bucket = blockIdx.y * NDIR + bdir;
    float* target = sc ? gacc3 : gacc;

    float cfrag[2][8][4];
#pragma unroll
    for (int mt = 0; mt < 2; mt++)
#pragma unroll
        for (int nt = 0; nt < 8; nt++)
#pragma unroll
            for (int j = 0; j < 4; j++) cfrag[mt][nt][j] = 0.f;

    auto load_A = [&](int c) {
        uint32_t aBase = sb + (uint32_t)c * 8192;
#pragma unroll
        for (int i = 0; i < 4; i++) {
            int idx = tid + (i << 7);          // 0..511
            int row = idx >> 3, g = idx & 7;   // row 0..63, 16B group
            uint32_t so = (uint32_t)row * 128 + (uint32_t)((g ^ (row & 7)) << 4);
            cp_async16(aBase + so, Ab + (size_t)(rowBase + row) * 128 + c * 64 + g * 8);
        }
    };
    auto load_B = [&]() {
#pragma unroll
        for (int i = 0; i < 16; i++) {
            int idx = tid + (i << 7);          // 0..2047
            int ch = idx >> 10;                // chunk 0/1
            int row = (idx >> 3) & 127, g = idx & 7;
            uint32_t so = 16384u + (uint32_t)ch * 16384 + (uint32_t)row * 128
                        + (uint32_t)((g ^ (row & 7)) << 4);
            cp_async16(sb + so, Bb + (size_t)(colBase + row) * 128 + ch * 64 + g * 8);
        }
    };

    load_B();
    load_A(0);
    cp_commit();
    load_A(1);
    cp_commit();

#pragma unroll
    for (int c = 0; c < 2; c++) {
        if (c == 0) cp_wait<1>();
        else        cp_wait<0>();
        __syncthreads();

        uint32_t aBase = sb + (uint32_t)c * 8192;
        uint32_t bBase = sb + 16384u + (uint32_t)c * 16384;

#pragma unroll
        for (int ks = 0; ks < 4; ks++) {
            uint32_t aF[2][4];
#pragma unroll
            for (int mt = 0; mt < 2; mt++) {
                int row = warpM * 32 + mt * 16 + (lane & 15);
                int g = ks * 2 + (lane >> 4);
                ldsm_x4(aF[mt], aBase + (uint32_t)row * 128 + (uint32_t)((g ^ (row & 7)) << 4));
            }
            uint32_t bF[8][2];
#pragma unroll
            for (int p = 0; p < 4; p++) {
                int n = warpN * 64 + p * 16 + ((lane >> 4) << 3) + (lane & 7);
                int g = ks * 2 + ((lane >> 3) & 1);
                uint32_t r[4];
                ldsm_x4(r, bBase + (uint32_t)n * 128 + (uint32_t)((g ^ (n & 7)) << 4));
                bF[2 * p][0] = r[0]; bF[2 * p][1] = r[1];
                bF[2 * p + 1][0] = r[2]; bF[2 * p + 1][1] = r[3];
            }
#pragma unroll
            for (int mt = 0; mt < 2; mt++)
#pragma unroll
                for (int nt = 0; nt < 8; nt++)
                    mma16816(cfrag[mt][nt], aF[mt], bF[nt]);
        }
    }
    __syncthreads();   // all ldsm reads done before Y-tile overwrite

    // ---- write Y tile to SMEM (512B contiguous rows) ----
    float* yt = reinterpret_cast<float*>(sdata);
#pragma unroll
    for (int mt = 0; mt < 2; mt++) {
        int r0 = warpM * 32 + mt * 16 + (lane >> 2);
#pragma unroll
        for (int nt = 0; nt < 8; nt++) {
            int c0 = warpN * 64 + nt * 8 + ((lane & 3) << 1);
            yt[r0 * YSTRIDE + c0]       = cfrag[mt][nt][0];
            yt[r0 * YSTRIDE + c0 + 1]   = cfrag[mt][nt][1];
            yt[(r0 + 8) * YSTRIDE + c0]     = cfrag[mt][nt][2];
            yt[(r0 + 8) * YSTRIDE + c0 + 1] = cfrag[mt][nt][3];
        }
    }
    __syncthreads();
    // order generic STS before async-proxy (TMA) reads of SMEM
    asm volatile("fence.proxy.async.shared::cta;" ::: "memory");

    // ---- scatter: one cp.reduce.async.bulk per edge (per-thread issue) ----
    const int e0 = __ldg(boffs + bucket);
    const int e1 = __ldg(boffs + bucket + 1);
    for (int e = e0 + tid; e < e1; e += 128) {
        uint32_t pk = __ldg(ebuf + e);
        uint32_t ls = (pk >> 16) & 63u;
        uint32_t dst = pk & 0xFFFFu;
        uint32_t saddr = sb + ls * 512u;
        float* gaddr = target + ((size_t)dst << 7);
        asm volatile(
            "cp.reduce.async.bulk.global.shared::cta.bulk_group.add.f32 [%0], [%1], 512;"
            :: "l"(gaddr), "r"(saddr) : "memory");
    }
    asm volatile("cp.async.bulk.commit_group;" ::: "memory");
    asm volatile("cp.async.bulk.wait_group 0;" ::: "memory");
}

// ---------------- edge bucketing (bucket = (srcTile64, sel)) ----------------
__global__ void hist_kernel(const int* __restrict__ src, const int* __restrict__ sel,
                            int* __restrict__ cnt, int E) {
    int i = blockIdx.x * blockDim.x + threadIdx.x;
    if (i >= E) return;
    int b = (__ldg(src + i) >> 6) * NDIR + __ldg(sel + i);
    atomicAdd(cnt + b, 1);
}

// 3-stage parallel scan over NBUCK=9216 (9 blocks x 256 threads x int4)
__global__ void scanA_kernel(const int* __restrict__ cnt, int* __restrict__ boffs,
                             int* __restrict__ part) {
    int t = threadIdx.x, lane = t & 31, wd = t >> 5;
    int base4 = blockIdx.x * 256 + t;
    int4 v = reinterpret_cast<const int4*>(cnt)[base4];
    int s0 = v.x, s01 = v.x + v.y, s012 = s01 + v.z, tsum = s012 + v.w;
    int inc = tsum;
#pragma unroll
    for (int off = 1; off < 32; off <<= 1) {
        int u = __shfl_up_sync(0xFFFFFFFFu, inc, off);
        if (lane >= off) inc += u;
    }
    __shared__ int wsum[8], wpf[8];
    if (lane == 31) wsum[wd] = inc;
    __syncthreads();
    if (t == 0) {
        int r = 0;
#pragma unroll
        for (int i = 0; i < 8; i++) { wpf[i] = r; r += wsum[i]; }
    }
    __syncthreads();
    int excl = wpf[wd] + inc - tsum;
    int4 o;
    o.x = excl; o.y = excl + s0; o.z = excl + s01; o.w = excl + s012;
    reinterpret_cast<int4*>(boffs)[base4] = o;
    if (t == 255) part[blockIdx.x] = excl + tsum;
}

__global__ void scanB_kernel(int* __restrict__ part, int* __restrict__ boffs_end) {
    if (threadIdx.x == 0) {
        int r = 0;
        for (int i = 0; i < 9; i++) { int v = part[i]; part[i] = r; r += v; }
        *boffs_end = r;
    }
}

__global__ void scanC_kernel(int* __restrict__ boffs, int* __restrict__ cur,
                             const int* __restrict__ part) {
    int i4 = blockIdx.x * 256 + threadIdx.x;
    int off = __ldg(part + blockIdx.x);
    int4 v = reinterpret_cast<int4*>(boffs)[i4];
    v.x += off; v.y += off; v.z += off; v.w += off;
    reinterpret_cast<int4*>(boffs)[i4] = v;
    reinterpret_cast<int4*>(cur)[i4] = v;
}

__global__ void fill_kernel(const int* __restrict__ src, const int* __restrict__ dst,
                            const int* __restrict__ sel, int* __restrict__ cur,
                            uint32_t* __restrict__ ebuf, int E) {
    int i = blockIdx.x * blockDim.x + threadIdx.x;
    if (i >= E) return;
    int s = __ldg(src + i);
    int b = (s >> 6) * NDIR + __ldg(sel + i);
    int p = atomicAdd(cur + b, 1);
    ebuf[p] = (uint32_t)(__ldg(dst + i) & 0xFFFF) | ((uint32_t)(s & 63) << 16);
}

// ---------------- prep kernels ----------------
__global__ void zero_both_kernel(float* __restrict__ a, float* __restrict__ b) {
    int i = blockIdx.x * blockDim.x + threadIdx.x;
    const int n4 = NNODES * 128 / 4;
    float4 z = make_float4(0.f, 0.f, 0.f, 0.f);
    if (i < n4) reinterpret_cast<float4*>(a)[i] = z;
    else if (i < 2 * n4) reinterpret_cast<float4*>(b)[i - n4] = z;
}

// X fp32 [N][128] -> fp16 [N][128]
__global__ void prepA_kernel(const float* __restrict__ X, __half* __restrict__ Ah) {
    int i = blockIdx.x * blockDim.x + threadIdx.x;
    if (i >= NNODES * 32) return;
    float4 x = reinterpret_cast<const float4*>(X)[i];
    reinterpret_cast<__half2*>(Ah)[i * 2] =
        __halves2half2(__float2half_rn(x.x), __float2half_rn(x.y));
    reinterpret_cast<__half2*>(Ah)[i * 2 + 1] =
        __halves2half2(__float2half_rn(x.z), __float2half_rn(x.w));
}

// all weights in one pass: W1 (9x128x128) -> WbA dirs 0-8; W2 -> Wb2; W3 -> WbA dir 9
__global__ void prepW_all_kernel(const float* __restrict__ W1, const float* __restrict__ W2,
                                 const float* __restrict__ W3,
                                 __half* __restrict__ WbA, __half* __restrict__ Wb2) {
    int idx = blockIdx.x * blockDim.x + threadIdx.x;
    if (idx < NW) {
        int d = idx >> 14, k = (idx >> 7) & 127, c = idx & 127;
        WbA[((size_t)d * 128 + c) * 128 + k] = __float2half_rn(W1[idx]);
    } else if (idx < 2 * NW) {
        int j = idx - NW;
        int d = j >> 14, k = (j >> 7) & 127, c = j & 127;
        Wb2[((size_t)d * 128 + c) * 128 + k] = __float2half_rn(W2[j]);
    } else if (idx < 2 * NW + 128 * 128) {
        int j = idx - 2 * NW;
        int k = j >> 7, c = j & 127;
        WbA[((size_t)NDIR * 128 + c) * 128 + k] = __float2half_rn(W3[j]);
    }
}

// ---------------- fused BN(eval) + ELU ----------------
// layer-1: acc -> fp16 features for layer 2; re-zero acc in place for reuse
__global__ void bnelu_prep_kernel(float* __restrict__ acc, const float* __restrict__ b,
                                  const float* __restrict__ g, const float* __restrict__ be,
                                  const float* __restrict__ rm, const float* __restrict__ rv,
                                  __half* __restrict__ Ah) {
    int i = blockIdx.x * blockDim.x + threadIdx.x;
    if (i >= NNODES * 128 / 4) return;
    float4 v = reinterpret_cast<const float4*>(acc)[i];
    int c0 = (i * 4) & 127;
    float o[4] = {v.x, v.y, v.z, v.w};
    float rr[4];
#pragma unroll
    for (int j = 0; j < 4; j++) {
        int c = c0 + j;
        float s = __ldg(g + c) * rsqrtf(__ldg(rv + c) + 1e-5f);
        float t = (o[j] + __ldg(b + c) - __ldg(rm + c)) * s + __ldg(be + c);
        rr[j] = elu1(t);
    }
    reinterpret_cast<__half2*>(Ah)[i * 2] =
        __halves2half2(__float2half_rn(rr[0]), __float2half_rn(rr[1]));
    reinterpret_cast<__half2*>(Ah)[i * 2 + 1] =
        __halves2half2(__float2half_rn(rr[2]), __float2half_rn(rr[3]));
    reinterpret_cast<float4*>(acc)[i] = make_float4(0.f, 0.f, 0.f, 0.f);
}

// fused layer-2 BN/ELU + shortcut combine + BN3/ELU:
// out = ELU(BN3( ELU(BN2(acc + b2)) + acc3 + b3 ))
__global__ void final2_kernel(const float* __restrict__ acc, const float* __restrict__ acc3,
                              const float* __restrict__ b2, const float* __restrict__ g2,
                              const float* __restrict__ be2, const float* __restrict__ rm2,
                              const float* __restrict__ rv2,
                              const float* __restrict__ b3, const float* __restrict__ g3,
                              const float* __restrict__ be3, const float* __restrict__ rm3,
                              const float* __restrict__ rv3,
                              float* __restrict__ out) {
    int i = blockIdx.x * blockDim.x + threadIdx.x;
    if (i >= NNODES * 128 / 4) return;
    float4 a = reinterpret_cast<const float4*>(acc)[i];
    float4 c4 = reinterpret_cast<const float4*>(acc3)[i];
    int c0 = (i * 4) & 127;
    float av[4] = {a.x, a.y, a.z, a.w};
    float sv[4] = {c4.x, c4.y, c4.z, c4.w};
    float4 r;
    float* rr = reinterpret_cast<float*>(&r);
#pragma unroll
    for (int j = 0; j < 4; j++) {
        int c = c0 + j;
        float s2 = __ldg(g2 + c) * rsqrtf(__ldg(rv2 + c) + 1e-5f);
        float h = elu1((av[j] + __ldg(b2 + c) - __ldg(rm2 + c)) * s2 + __ldg(be2 + c));
        float s3 = __ldg(g3 + c) * rsqrtf(__ldg(rv3 + c) + 1e-5f);
        float t = (h + sv[j] + __ldg(b3 + c) - __ldg(rm3 + c)) * s3 + __ldg(be3 + c);
        rr[j] = elu1(t);
    }
    reinterpret_cast<float4*>(out)[i] = r;
}

// ---------------- launch ----------------
extern "C" void kernel_launch(void* const* d_in, const int* in_sizes, int n_in,
                              void* d_out, int out_size) {
    const float* x   = (const float*)d_in[0];
    const int*   ei  = (const int*)d_in[1];
    const int*   sel = (const int*)d_in[2];
    const float* W1  = (const float*)d_in[3];
    const float* b1  = (const float*)d_in[4];
    const float* g1  = (const float*)d_in[5];
    const float* be1 = (const float*)d_in[6];
    const float* rm1 = (const float*)d_in[7];
    const float* rv1 = (const float*)d_in[8];
    const float* W2  = (const float*)d_in[9];
    const float* b2  = (const float*)d_in[10];
    const float* g2  = (const float*)d_in[11];
    const float* be2 = (const float*)d_in[12];
    const float* rm2 = (const float*)d_in[13];
    const float* rv2 = (const float*)d_in[14];
    const float* W3  = (const float*)d_in[15];
    const float* b3  = (const float*)d_in[16];
    const float* g3  = (const float*)d_in[17];
    const float* be3 = (const float*)d_in[18];
    const float* rm3 = (const float*)d_in[19];
    const float* rv3 = (const float*)d_in[20];
    float* out = (float*)d_out;

    const int E = in_sizes[2];
    const int* src = ei;
    const int* dst = ei + E;

    float *acc, *acc3;
    __half *Abx, *Abh, *WbA, *Wb2;
    int *cnt, *boffs, *cur, *part;
    uint32_t* ebuf;
    cudaGetSymbolAddress((void**)&acc, g_acc);
    cudaGetSymbolAddress((void**)&acc3, g_acc3);
    cudaGetSymbolAddress((void**)&Abx, g_Abx);
    cudaGetSymbolAddress((void**)&Abh, g_Abh);
    cudaGetSymbolAddress((void**)&WbA, g_WbA);
    cudaGetSymbolAddress((void**)&Wb2, g_Wb2);
    cudaGetSymbolAddress((void**)&cnt, g_cnt);
    cudaGetSymbolAddress((void**)&boffs, g_boffs);
    cudaGetSymbolAddress((void**)&cur, g_cur);
    cudaGetSymbolAddress((void**)&part, g_part);
    cudaGetSymbolAddress((void**)&ebuf, g_ebuf);

    cudaFuncSetAttribute(gemm_scatter_kernel<true>,
                         cudaFuncAttributeMaxDynamicSharedMemorySize, SMEM_BYTES);
    cudaFuncSetAttribute(gemm_scatter_kernel<false>,
                         cudaFuncAttributeMaxDynamicSharedMemorySize, SMEM_BYTES);

    const int nc4 = NNODES * 128 / 4;
    const int ew_blocks = (nc4 + 255) / 256;
    const int z2_blocks = (2 * nc4 + 255) / 256;
    const int prepA_blocks = (NNODES * 32 + 255) / 256;
    const int prepW_blocks = (2 * NW + 128 * 128 + 255) / 256;
    const int e_blocks = (E + 255) / 256;

    // ---- prep + bucketing ----
    cudaMemsetAsync(cnt, 0, NBUCK * sizeof(int));
    prepW_all_kernel<<<prepW_blocks, 256>>>(W1, W2, W3, WbA, Wb2);
    prepA_kernel<<<prepA_blocks, 256>>>(x, Abx);
    hist_kernel<<<e_blocks, 256>>>(src, sel, cnt, E);
    scanA_kernel<<<9, 256>>>(cnt, boffs, part);
    scanB_kernel<<<1, 32>>>(part, boffs + NBUCK);
    scanC_kernel<<<9, 256>>>(boffs, cur, part);
    fill_kernel<<<e_blocks, 256>>>(src, dst, sel, cur, ebuf, E);
    zero_both_kernel<<<z2_blocks, 256>>>(acc, acc3);

    // ---- layer 1 (9-dir) + shortcut (dir 9 = W3, sel-0 edges -> acc3) ----
    gemm_scatter_kernel<true><<<dim3(NDIR + 1, NTILES), 128, SMEM_BYTES>>>(
        Abx, WbA, boffs, ebuf, acc, acc3);
    bnelu_prep_kernel<<<ew_blocks, 256>>>(acc, b1, g1, be1, rm1, rv1, Abh);

    // ---- layer 2 (9-dir) ----
    gemm_scatter_kernel<false><<<dim3(NDIR, NTILES), 128, SMEM_BYTES>>>(
        Abh, Wb2, boffs, ebuf, acc, acc3);

    // ---- combine: ELU(BN3(ELU(BN2(acc+b2)) + acc3 + b3)) ----
    final2_kernel<<<ew_blocks, 256>>>(acc, acc3, b2, g2, be2, rm2, rv2,
                                      b3, g3, be3, rm3, rv3, out);
}

// round 15
// speedup vs baseline: 1.2509x; 1.2509x over previous
#include <cuda_runtime.h>
#include <cuda_fp16.h>
#include <cstdint>
#include <cstddef>

#define NNODES 65536
#define NDIR   9
#define NTILES (NNODES / 64)         // 1024 tiles of 64 nodes
#define NBUCK  (NTILES * NDIR)       // 9216
#define EMAX   1048576
#define NW     (NDIR * 128 * 128)

// ---------------- scratch (static device globals; no allocation) ----------------
__device__ __align__(256) __half g_accA[(size_t)NNODES * 128]; // even dirs
__device__ __align__(256) __half g_accB[(size_t)NNODES * 128]; // odd dirs
__device__ __align__(256) float  g_acc3[(size_t)NNODES * 128]; // shortcut (fp32, exact)
__device__ __align__(256) __half g_Abx[(size_t)NNODES * 128];
__device__ __align__(256) __half g_Abh[(size_t)NNODES * 128];
__device__ __align__(256) __half g_WbA[(size_t)(NDIR + 1) * 128 * 128]; // W1 dirs 0-8, W3 as dir 9
__device__ __align__(256) __half g_Wb2[(size_t)NW];
__device__ __align__(16) int g_cnt[NBUCK];
__device__ __align__(16) int g_boffs[NBUCK + 4];
__device__ __align__(16) int g_cur[NBUCK];
__device__ int g_part[16];
__device__ uint32_t g_ebuf[EMAX];    // packed: dst[0:16) | localsrc[16:22)

// ---------------- PTX helpers ----------------
__device__ __forceinline__ uint32_t smem_u32(const void* p) {
    uint32_t a;
    asm("{ .reg .u64 t; cvta.to.shared.u64 t, %1; cvt.u32.u64 %0, t; }" : "=r"(a) : "l"(p));
    return a;
}
__device__ __forceinline__ void cp_async16(uint32_t saddr, const void* gptr) {
    asm volatile("cp.async.cg.shared.global [%0], [%1], 16;" :: "r"(saddr), "l"(gptr) : "memory");
}
__device__ __forceinline__ void cp_commit() {
    asm volatile("cp.async.commit_group;" ::: "memory");
}
template <int N>
__device__ __forceinline__ void cp_wait() {
    asm volatile("cp.async.wait_group %0;" :: "n"(N) : "memory");
}
__device__ __forceinline__ void ldsm_x4(uint32_t* r, uint32_t addr) {
    asm volatile("ldmatrix.sync.aligned.m8n8.x4.shared.b16 {%0,%1,%2,%3}, [%4];"
                 : "=r"(r[0]), "=r"(r[1]), "=r"(r[2]), "=r"(r[3]) : "r"(addr));
}
__device__ __forceinline__ void mma16816(float* d, const uint32_t* a, const uint32_t* b) {
    asm volatile(
        "mma.sync.aligned.m16n8k16.row.col.f32.f16.f16.f32 "
        "{%0,%1,%2,%3}, {%4,%5,%6,%7}, {%8,%9}, {%0,%1,%2,%3};"
        : "+f"(d[0]), "+f"(d[1]), "+f"(d[2]), "+f"(d[3])
        : "r"(a[0]), "r"(a[1]), "r"(a[2]), "r"(a[3]), "r"(b[0]), "r"(b[1]));
}
__device__ __forceinline__ float elu1(float t) { return t > 0.f ? t : expm1f(t); }

// SMEM layout (dynamic, 1024-aligned base):
//   [0, 8K)   A chunk0 | [8K,16K) A chunk1 | [16K,32K) B chunk0 | [32K,48K) B chunk1
//   after mainloop, region reused as Y tile:
//     main dirs: fp16 [64][136] (17.4KB);  shortcut: fp32 [64][132] (33.8KB)
static constexpr int YSTRF = 132;    // fp32 Y stride (floats), shortcut path
static constexpr int YSTRH = 136;    // fp16 Y stride (halfs), main path (272B, 16B-mult)
static constexpr int SMEM_BYTES = 1024 + 49152;   // 50176 -> 4 CTAs/SM

// ---------------- fused GEMM + scatter ----------------
// grid = (ndirs, 1024). CTA computes Y tile [64 nodes x 128 cols] for weight block
// blockIdx.x (K=128 fp16).
// Main dirs: Y -> fp16 SMEM; scatter via red.global.add.noftz.v4.f16x2
//   (16 lanes/edge, 2 edges per warp-pass) into parity accumulator accA/accB.
// Shortcut (WITH_SC, blockIdx.x==NDIR): Y stays fp32; REDG v4.f32 into acc3.
template <bool WITH_SC>
__global__ void __launch_bounds__(128, 4)
gemm_scatter_kernel(const __half* __restrict__ Ab,   // [N][128] fp16
                    const __half* __restrict__ Bb,   // [(ndirs)*128][128] fp16, k contiguous
                    const int* __restrict__ boffs,
                    const uint32_t* __restrict__ ebuf,
                    __half* __restrict__ gaccA,
                    __half* __restrict__ gaccB,
                    float* __restrict__ gacc3)
{
    extern __shared__ char smem_raw[];
    char* sdata = (char*)(((uintptr_t)smem_raw + 1023) & ~(uintptr_t)1023);
    const uint32_t sb = smem_u32(sdata);

    const int tid = threadIdx.x;
    const int wid = tid >> 5, lane = tid & 31;
    const int warpM = wid & 1;        // 2 warps over M (32 rows each)
    const int warpN = wid >> 1;       // 2 warps over N (64 cols each)
    const int rowBase = blockIdx.y << 6;
    const int colBase = blockIdx.x << 7;   // weight row block
    const bool sc = WITH_SC && (blockIdx.x == NDIR);
    const int bdir = sc ? 0 : blockIdx.x;
    const int bucket = blockIdx.y * NDIR + bdir;

    float cfrag[2][8][4];
#pragma unroll
    for (int mt = 0; mt < 2; mt++)
#pragma unroll
        for (int nt = 0; nt < 8; nt++)
#pragma unroll
            for (int j = 0; j < 4; j++) cfrag[mt][nt][j] = 0.f;

    auto load_A = [&](int c) {
        uint32_t aBase = sb + (uint32_t)c * 8192;
#pragma unroll
        for (int i = 0; i < 4; i++) {
            int idx = tid + (i << 7);          // 0..511
            int row = idx >> 3, g = idx & 7;   // row 0..63, 16B group
            uint32_t so = (uint32_t)row * 128 + (uint32_t)((g ^ (row & 7)) << 4);
            cp_async16(aBase + so, Ab + (size_t)(rowBase + row) * 128 + c * 64 + g * 8);
        }
    };
    auto load_B = [&]() {
#pragma unroll
        for (int i = 0; i < 16; i++) {
            int idx = tid + (i << 7);          // 0..2047
            int ch = idx >> 10;                // chunk 0/1
            int row = (idx >> 3) & 127, g = idx & 7;
            uint32_t so = 16384u + (uint32_t)ch * 16384 + (uint32_t)row * 128
                        + (uint32_t)((g ^ (row & 7)) << 4);
            cp_async16(sb + so, Bb + (size_t)(colBase + row) * 128 + ch * 64 + g * 8);
        }
    };

    load_B();
    load_A(0);
    cp_commit();
    load_A(1);
    cp_commit();

#pragma unroll
    for (int c = 0; c < 2; c++) {
        if (c == 0) cp_wait<1>();
        else        cp_wait<0>();
        __syncthreads();

        uint32_t aBase = sb + (uint32_t)c * 8192;
        uint32_t bBase = sb + 16384u + (uint32_t)c * 16384;

#pragma unroll
        for (int ks = 0; ks < 4; ks++) {
            uint32_t aF[2][4];
#pragma unroll
            for (int mt = 0; mt < 2; mt++) {
                int row = warpM * 32 + mt * 16 + (lane & 15);
                int g = ks * 2 + (lane >> 4);
                ldsm_x4(aF[mt], aBase + (uint32_t)row * 128 + (uint32_t)((g ^ (row & 7)) << 4));
            }
            uint32_t bF[8][2];
#pragma unroll
            for (int p = 0; p < 4; p++) {
                int n = warpN * 64 + p * 16 + ((lane >> 4) << 3) + (lane & 7);
                int g = ks * 2 + ((lane >> 3) & 1);
                uint32_t r[4];
                ldsm_x4(r, bBase + (uint32_t)n * 128 + (uint32_t)((g ^ (n & 7)) << 4));
                bF[2 * p][0] = r[0]; bF[2 * p][1] = r[1];
                bF[2 * p + 1][0] = r[2]; bF[2 * p + 1][1] = r[3];
            }
#pragma unroll
            for (int mt = 0; mt < 2; mt++)
#pragma unroll
                for (int nt = 0; nt < 8; nt++)
                    mma16816(cfrag[mt][nt], aF[mt], bF[nt]);
        }
    }
    __syncthreads();   // all ldsm reads done before Y-tile overwrite

    const int e0 = __ldg(boffs + bucket);
    const int e1 = __ldg(boffs + bucket + 1);

    if (sc) {
        // ---- shortcut path: fp32 Y tile + REDG v4.f32 into acc3 (exact) ----
        float* yt = reinterpret_cast<float*>(sdata);
#pragma unroll
        for (int mt = 0; mt < 2; mt++) {
            int r0 = warpM * 32 + mt * 16 + (lane >> 2);
#pragma unroll
            for (int nt = 0; nt < 8; nt++) {
                int c0 = warpN * 64 + nt * 8 + ((lane & 3) << 1);
                yt[r0 * YSTRF + c0]       = cfrag[mt][nt][0];
                yt[r0 * YSTRF + c0 + 1]   = cfrag[mt][nt][1];
                yt[(r0 + 8) * YSTRF + c0]     = cfrag[mt][nt][2];
                yt[(r0 + 8) * YSTRF + c0 + 1] = cfrag[mt][nt][3];
            }
        }
        __syncthreads();
        for (int e = e0 + wid; e < e1; e += 4) {
            uint32_t pk = __ldg(ebuf + e);
            int ls = (pk >> 16) & 63;
            int dst = pk & 0xFFFF;
            float4 v = *reinterpret_cast<const float4*>(yt + (size_t)ls * YSTRF + lane * 4);
            float* op = gacc3 + (size_t)dst * 128 + lane * 4;
            asm volatile("red.global.add.v4.f32 [%0], {%1,%2,%3,%4};"
                         :: "l"(op), "f"(v.x), "f"(v.y), "f"(v.z), "f"(v.w)
                         : "memory");
        }
    } else {
        // ---- main path: fp16 Y tile + red.v4.f16x2, 2 edges per warp-pass ----
        __half* yh = reinterpret_cast<__half*>(sdata);
#pragma unroll
        for (int mt = 0; mt < 2; mt++) {
            int r0 = warpM * 32 + mt * 16 + (lane >> 2);
#pragma unroll
            for (int nt = 0; nt < 8; nt++) {
                int c0 = warpN * 64 + nt * 8 + ((lane & 3) << 1);
                *reinterpret_cast<__half2*>(yh + r0 * YSTRH + c0) =
                    __floats2half2_rn(cfrag[mt][nt][0], cfrag[mt][nt][1]);
                *reinterpret_cast<__half2*>(yh + (r0 + 8) * YSTRH + c0) =
                    __floats2half2_rn(cfrag[mt][nt][2], cfrag[mt][nt][3]);
            }
        }
        __syncthreads();
        __half* target = (bdir & 1) ? gaccB : gaccA;
        const int h = lane >> 4;       // half-warp id (0/1)
        const int l = lane & 15;       // lane within half-warp
        for (int e = e0 + wid * 2 + h; e < e1; e += 8) {
            uint32_t pk = __ldg(ebuf + e);
            int ls = (pk >> 16) & 63;
            int dst = pk & 0xFFFF;
            uint4 v = *reinterpret_cast<const uint4*>(yh + (size_t)ls * YSTRH + l * 8);
            __half* op = target + (size_t)dst * 128 + l * 8;
            asm volatile("red.global.add.noftz.v4.f16x2 [%0], {%1,%2,%3,%4};"
                         :: "l"(op), "r"(v.x), "r"(v.y), "r"(v.z), "r"(v.w)
                         : "memory");
        }
    }
}

// ---------------- edge bucketing (bucket = (srcTile64, sel)) ----------------
__global__ void hist_kernel(const int* __restrict__ src, const int* __restrict__ sel,
                            int* __restrict__ cnt, int E) {
    int i = blockIdx.x * blockDim.x + threadIdx.x;
    if (i >= E) return;
    int b = (__ldg(src + i) >> 6) * NDIR + __ldg(sel + i);
    atomicAdd(cnt + b, 1);
}

// 3-stage parallel scan over NBUCK=9216
__global__ void scanA_kernel(const int* __restrict__ cnt, int* __restrict__ boffs,
                             int* __restrict__ part) {
    int t = threadIdx.x, lane = t & 31, wd = t >> 5;
    int base4 = blockIdx.x * 256 + t;
    int4 v = reinterpret_cast<const int4*>(cnt)[base4];
    int s0 = v.x, s01 = v.x + v.y, s012 = s01 + v.z, tsum = s012 + v.w;
    int inc = tsum;
#pragma unroll
    for (int off = 1; off < 32; off <<= 1) {
        int u = __shfl_up_sync(0xFFFFFFFFu, inc, off);
        if (lane >= off) inc += u;
    }
    __shared__ int wsum[8], wpf[8];
    if (lane == 31) wsum[wd] = inc;
    __syncthreads();
    if (t == 0) {
        int r = 0;
#pragma unroll
        for (int i = 0; i < 8; i++) { wpf[i] = r; r += wsum[i]; }
    }
    __syncthreads();
    int excl = wpf[wd] + inc - tsum;
    int4 o;
    o.x = excl; o.y = excl + s0; o.z = excl + s01; o.w = excl + s012;
    reinterpret_cast<int4*>(boffs)[base4] = o;
    if (t == 255) part[blockIdx.x] = excl + tsum;
}

__global__ void scanB_kernel(int* __restrict__ part, int* __restrict__ boffs_end) {
    if (threadIdx.x == 0) {
        int r = 0;
        for (int i = 0; i < 9; i++) { int v = part[i]; part[i] = r; r += v; }
        *boffs_end = r;
    }
}

__global__ void scanC_kernel(int* __restrict__ boffs, int* __restrict__ cur,
                             const int* __restrict__ part) {
    int i4 = blockIdx.x * 256 + threadIdx.x;
    int off = __ldg(part + blockIdx.x);
    int4 v = reinterpret_cast<int4*>(boffs)[i4];
    v.x += off; v.y += off; v.z += off; v.w += off;
    reinterpret_cast<int4*>(boffs)[i4] = v;
    reinterpret_cast<int4*>(cur)[i4] = v;
}

__global__ void fill_kernel(const int* __restrict__ src, const int* __restrict__ dst,
                            const int* __restrict__ sel, int* __restrict__ cur,
                            uint32_t* __restrict__ ebuf, int E) {
    int i = blockIdx.x * blockDim.x + threadIdx.x;
    if (i >= E) return;
    int s = __ldg(src + i);
    int b = (s >> 6) * NDIR + __ldg(sel + i);
    int p = atomicAdd(cur + b, 1);
    ebuf[p] = (uint32_t)(__ldg(dst + i) & 0xFFFF) | ((uint32_t)(s & 63) << 16);
}

// ---------------- prep kernels ----------------
// zero accA, accB (fp16) and acc3 (fp32) in one pass
__global__ void zero_accs_kernel(__half* __restrict__ a, __half* __restrict__ b,
                                 float* __restrict__ c) {
    int i = blockIdx.x * blockDim.x + threadIdx.x;
    const int nh4 = NNODES * 128 / 8;   // uint4 count for fp16 buffers
    const int nf4 = NNODES * 128 / 4;   // float4 count for fp32 buffer
    uint4 z = make_uint4(0, 0, 0, 0);
    if (i < nh4) reinterpret_cast<uint4*>(a)[i] = z;
    else if (i < 2 * nh4) reinterpret_cast<uint4*>(b)[i - nh4] = z;
    else if (i < 2 * nh4 + nf4)
        reinterpret_cast<float4*>(c)[i - 2 * nh4] = make_float4(0.f, 0.f, 0.f, 0.f);
}

// X fp32 [N][128] -> fp16 [N][128]
__global__ void prepA_kernel(const float* __restrict__ X, __half* __restrict__ Ah) {
    int i = blockIdx.x * blockDim.x + threadIdx.x;
    if (i >= NNODES * 32) return;
    float4 x = reinterpret_cast<const float4*>(X)[i];
    reinterpret_cast<__half2*>(Ah)[i * 2] =
        __halves2half2(__float2half_rn(x.x), __float2half_rn(x.y));
    reinterpret_cast<__half2*>(Ah)[i * 2 + 1] =
        __halves2half2(__float2half_rn(x.z), __float2half_rn(x.w));
}

// all weights in one pass: W1 (9x128x128) -> WbA dirs 0-8; W2 -> Wb2; W3 -> WbA dir 9
__global__ void prepW_all_kernel(const float* __restrict__ W1, const float* __restrict__ W2,
                                 const float* __restrict__ W3,
                                 __half* __restrict__ WbA, __half* __restrict__ Wb2) {
    int idx = blockIdx.x * blockDim.x + threadIdx.x;
    if (idx < NW) {
        int d = idx >> 14, k = (idx >> 7) & 127, c = idx & 127;
        WbA[((size_t)d * 128 + c) * 128 + k] = __float2half_rn(W1[idx]);
    } else if (idx < 2 * NW) {
        int j = idx - NW;
        int d = j >> 14, k = (j >> 7) & 127, c = j & 127;
        Wb2[((size_t)d * 128 + c) * 128 + k] = __float2half_rn(W2[j]);
    } else if (idx < 2 * NW + 128 * 128) {
        int j = idx - 2 * NW;
        int k = j >> 7, c = j & 127;
        WbA[((size_t)NDIR * 128 + c) * 128 + k] = __float2half_rn(W3[j]);
    }
}

// ---------------- fused BN(eval) + ELU ----------------
// layer-1: (accA+accB) -> fp16 features for layer 2; re-zero accs in place
__global__ void bnelu_prep_kernel(__half* __restrict__ accA, __half* __restrict__ accB,
                                  const float* __restrict__ b,
                                  const float* __restrict__ g, const float* __restrict__ be,
                                  const float* __restrict__ rm, const float* __restrict__ rv,
                                  __half* __restrict__ Ah) {
    int i = blockIdx.x * blockDim.x + threadIdx.x;   // 8 halfs per thread
    if (i >= NNODES * 16) return;
    uint4 va = reinterpret_cast<const uint4*>(accA)[i];
    uint4 vb = reinterpret_cast<const uint4*>(accB)[i];
    const uint32_t* pa = reinterpret_cast<const uint32_t*>(&va);
    const uint32_t* pb = reinterpret_cast<const uint32_t*>(&vb);
    int c0 = (i * 8) & 127;
    uint4 o;
    uint32_t* po = reinterpret_cast<uint32_t*>(&o);
#pragma unroll
    for (int q = 0; q < 4; q++) {
        float2 fa = __half22float2(*reinterpret_cast<const __half2*>(pa + q));
        float2 fb = __half22float2(*reinterpret_cast<const __half2*>(pb + q));
        int c = c0 + q * 2;
        float s0 = __ldg(g + c) * rsqrtf(__ldg(rv + c) + 1e-5f);
        float s1 = __ldg(g + c + 1) * rsqrtf(__ldg(rv + c + 1) + 1e-5f);
        float t0 = (fa.x + fb.x + __ldg(b + c) - __ldg(rm + c)) * s0 + __ldg(be + c);
        float t1 = (fa.y + fb.y + __ldg(b + c + 1) - __ldg(rm + c + 1)) * s1 + __ldg(be + c + 1);
        __half2 h = __floats2half2_rn(elu1(t0), elu1(t1));
        po[q] = *reinterpret_cast<uint32_t*>(&h);
    }
    reinterpret_cast<uint4*>(Ah)[i] = o;
    uint4 z = make_uint4(0, 0, 0, 0);
    reinterpret_cast<uint4*>(accA)[i] = z;
    reinterpret_cast<uint4*>(accB)[i] = z;
}

// out = ELU(BN3( ELU(BN2(accA+accB + b2)) + acc3 + b3 ))
__global__ void final2_kernel(const __half* __restrict__ accA, const __half* __restrict__ accB,
                              const float* __restrict__ acc3,
                              const float* __restrict__ b2, const float* __restrict__ g2,
                              const float* __restrict__ be2, const float* __restrict__ rm2,
                              const float* __restrict__ rv2,
                              const float* __restrict__ b3, const float* __restrict__ g3,
                              const float* __restrict__ be3, const float* __restrict__ rm3,
                              const float* __restrict__ rv3,
                              float* __restrict__ out) {
    int i = blockIdx.x * blockDim.x + threadIdx.x;   // 8 elems per thread
    if (i >= NNODES * 16) return;
    uint4 va = reinterpret_cast<const uint4*>(accA)[i];
    uint4 vb = reinterpret_cast<const uint4*>(accB)[i];
    const uint32_t* pa = reinterpret_cast<const uint32_t*>(&va);
    const uint32_t* pb = reinterpret_cast<const uint32_t*>(&vb);
    float4 s3a = reinterpret_cast<const float4*>(acc3)[i * 2];
    float4 s3b = reinterpret_cast<const float4*>(acc3)[i * 2 + 1];
    const float* sv = reinterpret_cast<const float*>(&s3a);   // s3a,s3b contiguous on stack
    float svv[8] = {s3a.x, s3a.y, s3a.z, s3a.w, s3b.x, s3b.y, s3b.z, s3b.w};
    (void)sv;
    int c0 = (i * 8) & 127;
    float ro[8];
#pragma unroll
    for (int q = 0; q < 4; q++) {
        float2 fa = __half22float2(*reinterpret_cast<const __half2*>(pa + q));
        float2 fb = __half22float2(*reinterpret_cast<const __half2*>(pb + q));
        float acc0 = fa.x + fb.x;
        float acc1 = fa.y + fb.y;
#pragma unroll
        for (int j = 0; j < 2; j++) {
            int c = c0 + q * 2 + j;
            float accv = (j == 0) ? acc0 : acc1;
            float s2 = __ldg(g2 + c) * rsqrtf(__ldg(rv2 + c) + 1e-5f);
            float h = elu1((accv + __ldg(b2 + c) - __ldg(rm2 + c)) * s2 + __ldg(be2 + c));
            float s3 = __ldg(g3 + c) * rsqrtf(__ldg(rv3 + c) + 1e-5f);
            float t = (h + svv[q * 2 + j] + __ldg(b3 + c) - __ldg(rm3 + c)) * s3 + __ldg(be3 + c);
            ro[q * 2 + j] = elu1(t);
        }
    }
    float4 o0 = make_float4(ro[0], ro[1], ro[2], ro[3]);
    float4 o1 = make_float4(ro[4], ro[5], ro[6], ro[7]);
    reinterpret_cast<float4*>(out)[i * 2] = o0;
    reinterpret_cast<float4*>(out)[i * 2 + 1] = o1;
}

// ---------------- launch ----------------
extern "C" void kernel_launch(void* const* d_in, const int* in_sizes, int n_in,
                              void* d_out, int out_size) {
    const float* x   = (const float*)d_in[0];
    const int*   ei  = (const int*)d_in[1];
    const int*   sel = (const int*)d_in[2];
    const float* W1  = (const float*)d_in[3];
    const float* b1  = (const float*)d_in[4];
    const float* g1  = (const float*)d_in[5];
    const float* be1 = (const float*)d_in[6];
    const float* rm1 = (const float*)d_in[7];
    const float* rv1 = (const float*)d_in[8];
    const float* W2  = (const float*)d_in[9];
    const float* b2  = (const float*)d_in[10];
    const float* g2  = (const float*)d_in[11];
    const float* be2 = (const float*)d_in[12];
    const float* rm2 = (const float*)d_in[13];
    const float* rv2 = (const float*)d_in[14];
    const float* W3  = (const float*)d_in[15];
    const float* b3  = (const float*)d_in[16];
    const float* g3  = (const float*)d_in[17];
    const float* be3 = (const float*)d_in[18];
    const float* rm3 = (const float*)d_in[19];
    const float* rv3 = (const float*)d_in[20];
    float* out = (float*)d_out;

    const int E = in_sizes[2];
    const int* src = ei;
    const int* dst = ei + E;

    __half *accA, *accB, *Abx, *Abh, *WbA, *Wb2;
    float* acc3;
    int *cnt, *boffs, *cur, *part;
    uint32_t* ebuf;
    cudaGetSymbolAddress((void**)&accA, g_accA);
    cudaGetSymbolAddress((void**)&accB, g_accB);
    cudaGetSymbolAddress((void**)&acc3, g_acc3);
    cudaGetSymbolAddress((void**)&Abx, g_Abx);
    cudaGetSymbolAddress((void**)&Abh, g_Abh);
    cudaGetSymbolAddress((void**)&WbA, g_WbA);
    cudaGetSymbolAddress((void**)&Wb2, g_Wb2);
    cudaGetSymbolAddress((void**)&cnt, g_cnt);
    cudaGetSymbolAddress((void**)&boffs, g_boffs);
    cudaGetSymbolAddress((void**)&cur, g_cur);
    cudaGetSymbolAddress((void**)&part, g_part);
    cudaGetSymbolAddress((void**)&ebuf, g_ebuf);

    cudaFuncSetAttribute(gemm_scatter_kernel<true>,
                         cudaFuncAttributeMaxDynamicSharedMemorySize, SMEM_BYTES);
    cudaFuncSetAttribute(gemm_scatter_kernel<false>,
                         cudaFuncAttributeMaxDynamicSharedMemorySize, SMEM_BYTES);

    const int nh4 = NNODES * 128 / 8;
    const int nf4 = NNODES * 128 / 4;
    const int z_blocks = (2 * nh4 + nf4 + 255) / 256;
    const int ew_blocks = (NNODES * 16 + 255) / 256;
    const int prepA_blocks = (NNODES * 32 + 255) / 256;
    const int prepW_blocks = (2 * NW + 128 * 128 + 255) / 256;
    const int e_blocks = (E + 255) / 256;

    // ---- prep + bucketing ----
    cudaMemsetAsync(cnt, 0, NBUCK * sizeof(int));
    prepW_all_kernel<<<prepW_blocks, 256>>>(W1, W2, W3, WbA, Wb2);
    prepA_kernel<<<prepA_blocks, 256>>>(x, Abx);
    hist_kernel<<<e_blocks, 256>>>(src, sel, cnt, E);
    scanA_kernel<<<9, 256>>>(cnt, boffs, part);
    scanB_kernel<<<1, 32>>>(part, boffs + NBUCK);
    scanC_kernel<<<9, 256>>>(boffs, cur, part);
    fill_kernel<<<e_blocks, 256>>>(src, dst, sel, cur, ebuf, E);
    zero_accs_kernel<<<z_blocks, 256>>>(accA, accB, acc3);

    // ---- layer 1 (9-dir -> accA/accB) + shortcut (dir 9 = W3 -> acc3, fp32) ----
    gemm_scatter_kernel<true><<<dim3(NDIR + 1, NTILES), 128, SMEM_BYTES>>>(
        Abx, WbA, boffs, ebuf, accA, accB, acc3);
    bnelu_prep_kernel<<<ew_blocks, 256>>>(accA, accB, b1, g1, be1, rm1, rv1, Abh);

    // ---- layer 2 (9-dir -> accA/accB) ----
    gemm_scatter_kernel<false><<<dim3(NDIR, NTILES), 128, SMEM_BYTES>>>(
        Abh, Wb2, boffs, ebuf, accA, accB, acc3);

    // ---- combine: ELU(BN3(ELU(BN2(accA+accB+b2)) + acc3 + b3)) ----
    final2_kernel<<<ew_blocks, 256>>>(accA, accB, acc3, b2, g2, be2, rm2, rv2,
                                      b3, g3, be3, rm3, rv3, out);
}

// round 16
// speedup vs baseline: 1.2917x; 1.0326x over previous
#include <cuda_runtime.h>
#include <cuda_fp16.h>
#include <cstdint>
#include <cstddef>

#define NNODES 65536
#define NDIR   9
#define NTILES (NNODES / 64)         // 1024 tiles of 64 nodes
#define NBUCK  (NTILES * NDIR)       // 9216
#define EMAX   1048576
#define NW     (NDIR * 128 * 128)

// ---------------- scratch (static device globals; no allocation) ----------------
__device__ __align__(256) __half g_accA[(size_t)NNODES * 128]; // even dirs
__device__ __align__(256) __half g_accB[(size_t)NNODES * 128]; // odd dirs
__device__ __align__(256) float  g_acc3[(size_t)NNODES * 128]; // shortcut (fp32, exact)
__device__ __align__(256) __half g_Abx[(size_t)NNODES * 128];
__device__ __align__(256) __half g_Abh[(size_t)NNODES * 128];
__device__ __align__(256) __half g_WbA[(size_t)(NDIR + 1) * 128 * 128]; // W1 dirs 0-8, W3 as dir 9
__device__ __align__(256) __half g_Wb2[(size_t)NW];
__device__ __align__(16) int g_cnt[NBUCK];
__device__ __align__(16) int g_boffs[NBUCK + 4];
__device__ __align__(16) int g_cur[NBUCK];
__device__ int g_part[16];
__device__ uint32_t g_ebuf[EMAX];    // packed: dst[0:16) | localsrc[16:22)

// ---------------- PTX helpers ----------------
__device__ __forceinline__ uint32_t smem_u32(const void* p) {
    uint32_t a;
    asm("{ .reg .u64 t; cvta.to.shared.u64 t, %1; cvt.u32.u64 %0, t; }" : "=r"(a) : "l"(p));
    return a;
}
__device__ __forceinline__ void cp_async16(uint32_t saddr, const void* gptr) {
    asm volatile("cp.async.cg.shared.global [%0], [%1], 16;" :: "r"(saddr), "l"(gptr) : "memory");
}
__device__ __forceinline__ void cp_commit() {
    asm volatile("cp.async.commit_group;" ::: "memory");
}
template <int N>
__device__ __forceinline__ void cp_wait() {
    asm volatile("cp.async.wait_group %0;" :: "n"(N) : "memory");
}
__device__ __forceinline__ void ldsm_x4(uint32_t* r, uint32_t addr) {
    asm volatile("ldmatrix.sync.aligned.m8n8.x4.shared.b16 {%0,%1,%2,%3}, [%4];"
                 : "=r"(r[0]), "=r"(r[1]), "=r"(r[2]), "=r"(r[3]) : "r"(addr));
}
__device__ __forceinline__ void mma16816(float* d, const uint32_t* a, const uint32_t* b) {
    asm volatile(
        "mma.sync.aligned.m16n8k16.row.col.f32.f16.f16.f32 "
        "{%0,%1,%2,%3}, {%4,%5,%6,%7}, {%8,%9}, {%0,%1,%2,%3};"
        : "+f"(d[0]), "+f"(d[1]), "+f"(d[2]), "+f"(d[3])
        : "r"(a[0]), "r"(a[1]), "r"(a[2]), "r"(a[3]), "r"(b[0]), "r"(b[1]));
}
__device__ __forceinline__ float elu1(float t) { return t > 0.f ? t : expm1f(t); }

// SMEM layout (dynamic, 1024-aligned base):
//   [0, 8K)   A chunk0 | [8K,16K) A chunk1 | [16K,32K) B chunk0 | [32K,48K) B chunk1
//   after mainloop, region reused as Y tile:
//     main dirs: fp16 [64][136] (17.4KB);  shortcut: fp32 [64][132] (33.8KB)
static constexpr int YSTRF = 132;    // fp32 Y stride (floats), shortcut path
static constexpr int YSTRH = 136;    // fp16 Y stride (halfs), main path
static constexpr int SMEM_BYTES = 1024 + 49152;   // 50176 -> 4 CTAs/SM

// ---------------- fused GEMM + scatter (round-15 champion, unchanged) ----------------
template <bool WITH_SC>
__global__ void __launch_bounds__(128, 4)
gemm_scatter_kernel(const __half* __restrict__ Ab,
                    const __half* __restrict__ Bb,
                    const int* __restrict__ boffs,
                    const uint32_t* __restrict__ ebuf,
                    __half* __restrict__ gaccA,
                    __half* __restrict__ gaccB,
                    float* __restrict__ gacc3)
{
    extern __shared__ char smem_raw[];
    char* sdata = (char*)(((uintptr_t)smem_raw + 1023) & ~(uintptr_t)1023);
    const uint32_t sb = smem_u32(sdata);

    const int tid = threadIdx.x;
    const int wid = tid >> 5, lane = tid & 31;
    const int warpM = wid & 1;
    const int warpN = wid >> 1;
    const int rowBase = blockIdx.y << 6;
    const int colBase = blockIdx.x << 7;
    const bool sc = WITH_SC && (blockIdx.x == NDIR);
    const int bdir = sc ? 0 : blockIdx.x;
    const int bucket = blockIdx.y * NDIR + bdir;

    float cfrag[2][8][4];
#pragma unroll
    for (int mt = 0; mt < 2; mt++)
#pragma unroll
        for (int nt = 0; nt < 8; nt++)
#pragma unroll
            for (int j = 0; j < 4; j++) cfrag[mt][nt][j] = 0.f;

    auto load_A = [&](int c) {
        uint32_t aBase = sb + (uint32_t)c * 8192;
#pragma unroll
        for (int i = 0; i < 4; i++) {
            int idx = tid + (i << 7);
            int row = idx >> 3, g = idx & 7;
            uint32_t so = (uint32_t)row * 128 + (uint32_t)((g ^ (row & 7)) << 4);
            cp_async16(aBase + so, Ab + (size_t)(rowBase + row) * 128 + c * 64 + g * 8);
        }
    };
    auto load_B = [&]() {
#pragma unroll
        for (int i = 0; i < 16; i++) {
            int idx = tid + (i << 7);
            int ch = idx >> 10;
            int row = (idx >> 3) & 127, g = idx & 7;
            uint32_t so = 16384u + (uint32_t)ch * 16384 + (uint32_t)row * 128
                        + (uint32_t)((g ^ (row & 7)) << 4);
            cp_async16(sb + so, Bb + (size_t)(colBase + row) * 128 + ch * 64 + g * 8);
        }
    };

    load_B();
    load_A(0);
    cp_commit();
    load_A(1);
    cp_commit();

#pragma unroll
    for (int c = 0; c < 2; c++) {
        if (c == 0) cp_wait<1>();
        else        cp_wait<0>();
        __syncthreads();

        uint32_t aBase = sb + (uint32_t)c * 8192;
        uint32_t bBase = sb + 16384u + (uint32_t)c * 16384;

#pragma unroll
        for (int ks = 0; ks < 4; ks++) {
            uint32_t aF[2][4];
#pragma unroll
            for (int mt = 0; mt < 2; mt++) {
                int row = warpM * 32 + mt * 16 + (lane & 15);
                int g = ks * 2 + (lane >> 4);
                ldsm_x4(aF[mt], aBase + (uint32_t)row * 128 + (uint32_t)((g ^ (row & 7)) << 4));
            }
            uint32_t bF[8][2];
#pragma unroll
            for (int p = 0; p < 4; p++) {
                int n = warpN * 64 + p * 16 + ((lane >> 4) << 3) + (lane & 7);
                int g = ks * 2 + ((lane >> 3) & 1);
                uint32_t r[4];
                ldsm_x4(r, bBase + (uint32_t)n * 128 + (uint32_t)((g ^ (n & 7)) << 4));
                bF[2 * p][0] = r[0]; bF[2 * p][1] = r[1];
                bF[2 * p + 1][0] = r[2]; bF[2 * p + 1][1] = r[3];
            }
#pragma unroll
            for (int mt = 0; mt < 2; mt++)
#pragma unroll
                for (int nt = 0; nt < 8; nt++)
                    mma16816(cfrag[mt][nt], aF[mt], bF[nt]);
        }
    }
    __syncthreads();

    const int e0 = __ldg(boffs + bucket);
    const int e1 = __ldg(boffs + bucket + 1);

    if (sc) {
        // shortcut: fp32 Y tile + REDG v4.f32 into acc3 (exact)
        float* yt = reinterpret_cast<float*>(sdata);
#pragma unroll
        for (int mt = 0; mt < 2; mt++) {
            int r0 = warpM * 32 + mt * 16 + (lane >> 2);
#pragma unroll
            for (int nt = 0; nt < 8; nt++) {
                int c0 = warpN * 64 + nt * 8 + ((lane & 3) << 1);
                yt[r0 * YSTRF + c0]       = cfrag[mt][nt][0];
                yt[r0 * YSTRF + c0 + 1]   = cfrag[mt][nt][1];
                yt[(r0 + 8) * YSTRF + c0]     = cfrag[mt][nt][2];
                yt[(r0 + 8) * YSTRF + c0 + 1] = cfrag[mt][nt][3];
            }
        }
        __syncthreads();
        for (int e = e0 + wid; e < e1; e += 4) {
            uint32_t pk = __ldg(ebuf + e);
            int ls = (pk >> 16) & 63;
            int dst = pk & 0xFFFF;
            float4 v = *reinterpret_cast<const float4*>(yt + (size_t)ls * YSTRF + lane * 4);
            float* op = gacc3 + (size_t)dst * 128 + lane * 4;
            asm volatile("red.global.add.v4.f32 [%0], {%1,%2,%3,%4};"
                         :: "l"(op), "f"(v.x), "f"(v.y), "f"(v.z), "f"(v.w)
                         : "memory");
        }
    } else {
        // main: fp16 Y tile + red.v4.f16x2 (16 lanes/edge, 2 edges/warp-pass)
        __half* yh = reinterpret_cast<__half*>(sdata);
#pragma unroll
        for (int mt = 0; mt < 2; mt++) {
            int r0 = warpM * 32 + mt * 16 + (lane >> 2);
#pragma unroll
            for (int nt = 0; nt < 8; nt++) {
                int c0 = warpN * 64 + nt * 8 + ((lane & 3) << 1);
                *reinterpret_cast<__half2*>(yh + r0 * YSTRH + c0) =
                    __floats2half2_rn(cfrag[mt][nt][0], cfrag[mt][nt][1]);
                *reinterpret_cast<__half2*>(yh + (r0 + 8) * YSTRH + c0) =
                    __floats2half2_rn(cfrag[mt][nt][2], cfrag[mt][nt][3]);
            }
        }
        __syncthreads();
        __half* target = (bdir & 1) ? gaccB : gaccA;
        const int h = lane >> 4;
        const int l = lane & 15;
        for (int e = e0 + wid * 2 + h; e < e1; e += 8) {
            uint32_t pk = __ldg(ebuf + e);
            int ls = (pk >> 16) & 63;
            int dst = pk & 0xFFFF;
            uint4 v = *reinterpret_cast<const uint4*>(yh + (size_t)ls * YSTRH + l * 8);
            __half* op = target + (size_t)dst * 128 + l * 8;
            asm volatile("red.global.add.noftz.v4.f16x2 [%0], {%1,%2,%3,%4};"
                         :: "l"(op), "r"(v.x), "r"(v.y), "r"(v.z), "r"(v.w)
                         : "memory");
        }
    }
}

// ---------------- merged prep: cnt zero + W1/W2/W3 fp16 pack + x fp16 ----------------
__global__ void prep_all_kernel(const float* __restrict__ W1, const float* __restrict__ W2,
                                const float* __restrict__ W3, const float* __restrict__ X,
                                __half* __restrict__ WbA, __half* __restrict__ Wb2,
                                __half* __restrict__ Ah, int* __restrict__ cnt) {
    int idx = blockIdx.x * blockDim.x + threadIdx.x;
    if (idx < NW) {
        int d = idx >> 14, k = (idx >> 7) & 127, c = idx & 127;
        WbA[((size_t)d * 128 + c) * 128 + k] = __float2half_rn(W1[idx]);
    } else if (idx < 2 * NW) {
        int j = idx - NW;
        int d = j >> 14, k = (j >> 7) & 127, c = j & 127;
        Wb2[((size_t)d * 128 + c) * 128 + k] = __float2half_rn(W2[j]);
    } else if (idx < 2 * NW + 128 * 128) {
        int j = idx - 2 * NW;
        int k = j >> 7, c = j & 127;
        WbA[((size_t)NDIR * 128 + c) * 128 + k] = __float2half_rn(W3[j]);
    } else if (idx < 2 * NW + 128 * 128 + NNODES * 32) {
        int i = idx - (2 * NW + 128 * 128);
        float4 x = reinterpret_cast<const float4*>(X)[i];
        reinterpret_cast<__half2*>(Ah)[i * 2] =
            __halves2half2(__float2half_rn(x.x), __float2half_rn(x.y));
        reinterpret_cast<__half2*>(Ah)[i * 2 + 1] =
            __halves2half2(__float2half_rn(x.z), __float2half_rn(x.w));
    } else if (idx < 2 * NW + 128 * 128 + NNODES * 32 + NBUCK) {
        cnt[idx - (2 * NW + 128 * 128 + NNODES * 32)] = 0;
    }
}

// ---------------- hist + accumulator zeroing fused ----------------
__global__ void hist_zero_kernel(const int* __restrict__ src, const int* __restrict__ sel,
                                 int* __restrict__ cnt, int E,
                                 __half* __restrict__ accA, __half* __restrict__ accB,
                                 float* __restrict__ acc3) {
    int i = blockIdx.x * blockDim.x + threadIdx.x;
    int nthreads = gridDim.x * blockDim.x;
    if (i < E) {
        int b = (__ldg(src + i) >> 6) * NDIR + __ldg(sel + i);
        atomicAdd(cnt + b, 1);
    }
    // grid-stride zero of 96MB: accA/accB fp16 (2M uint4 each) + acc3 fp32 (2M float4)
    const int nh4 = NNODES * 128 / 8;
    const int nf4 = NNODES * 128 / 4;
    uint4 z = make_uint4(0, 0, 0, 0);
    for (int j = i; j < 2 * nh4 + nf4; j += nthreads) {
        if (j < nh4) reinterpret_cast<uint4*>(accA)[j] = z;
        else if (j < 2 * nh4) reinterpret_cast<uint4*>(accB)[j - nh4] = z;
        else reinterpret_cast<float4*>(acc3)[j - 2 * nh4] = make_float4(0.f, 0.f, 0.f, 0.f);
    }
}

// ---------------- scan: 2 stages (scanA raw block sums; scanC local 9-int prefix) ----------------
__global__ void scanA_kernel(const int* __restrict__ cnt, int* __restrict__ boffs,
                             int* __restrict__ part) {
    int t = threadIdx.x, lane = t & 31, wd = t >> 5;
    int base4 = blockIdx.x * 256 + t;
    int4 v = reinterpret_cast<const int4*>(cnt)[base4];
    int s0 = v.x, s01 = v.x + v.y, s012 = s01 + v.z, tsum = s012 + v.w;
    int inc = tsum;
#pragma unroll
    for (int off = 1; off < 32; off <<= 1) {
        int u = __shfl_up_sync(0xFFFFFFFFu, inc, off);
        if (lane >= off) inc += u;
    }
    __shared__ int wsum[8], wpf[8];
    if (lane == 31) wsum[wd] = inc;
    __syncthreads();
    if (t == 0) {
        int r = 0;
#pragma unroll
        for (int i = 0; i < 8; i++) { wpf[i] = r; r += wsum[i]; }
    }
    __syncthreads();
    int excl = wpf[wd] + inc - tsum;
    int4 o;
    o.x = excl; o.y = excl + s0; o.z = excl + s01; o.w = excl + s012;
    reinterpret_cast<int4*>(boffs)[base4] = o;
    if (t == 255) part[blockIdx.x] = excl + tsum;   // raw block sum
}

__global__ void scanC_kernel(int* __restrict__ boffs, int* __restrict__ cur,
                             const int* __restrict__ part) {
    // each block locally computes the exclusive prefix of the 9 raw block sums
    __shared__ int off_s, tot_s;
    if (threadIdx.x == 0) {
        int r = 0, mine = 0, tot = 0;
#pragma unroll
        for (int i = 0; i < 9; i++) {
            int v = __ldg(part + i);
            if (i == (int)blockIdx.x) mine = r;
            r += v;
            tot = r;
        }
        off_s = mine;
        tot_s = tot;
    }
    __syncthreads();
    int off = off_s;
    int i4 = blockIdx.x * 256 + threadIdx.x;
    int4 v = reinterpret_cast<int4*>(boffs)[i4];
    v.x += off; v.y += off; v.z += off; v.w += off;
    reinterpret_cast<int4*>(boffs)[i4] = v;
    reinterpret_cast<int4*>(cur)[i4] = v;
    if (blockIdx.x == 8 && threadIdx.x == 255) boffs[NBUCK] = tot_s;
}

__global__ void fill_kernel(const int* __restrict__ src, const int* __restrict__ dst,
                            const int* __restrict__ sel, int* __restrict__ cur,
                            uint32_t* __restrict__ ebuf, int E) {
    int i = blockIdx.x * blockDim.x + threadIdx.x;
    if (i >= E) return;
    int s = __ldg(src + i);
    int b = (s >> 6) * NDIR + __ldg(sel + i);
    int p = atomicAdd(cur + b, 1);
    ebuf[p] = (uint32_t)(__ldg(dst + i) & 0xFFFF) | ((uint32_t)(s & 63) << 16);
}

// ---------------- fused BN(eval) + ELU ----------------
// layer-1: (accA+accB) -> fp16 features for layer 2; re-zero accs in place
__global__ void bnelu_prep_kernel(__half* __restrict__ accA, __half* __restrict__ accB,
                                  const float* __restrict__ b,
                                  const float* __restrict__ g, const float* __restrict__ be,
                                  const float* __restrict__ rm, const float* __restrict__ rv,
                                  __half* __restrict__ Ah) {
    int i = blockIdx.x * blockDim.x + threadIdx.x;
    if (i >= NNODES * 16) return;
    uint4 va = reinterpret_cast<const uint4*>(accA)[i];
    uint4 vb = reinterpret_cast<const uint4*>(accB)[i];
    const uint32_t* pa = reinterpret_cast<const uint32_t*>(&va);
    const uint32_t* pb = reinterpret_cast<const uint32_t*>(&vb);
    int c0 = (i * 8) & 127;
    uint4 o;
    uint32_t* po = reinterpret_cast<uint32_t*>(&o);
#pragma unroll
    for (int q = 0; q < 4; q++) {
        float2 fa = __half22float2(*reinterpret_cast<const __half2*>(pa + q));
        float2 fb = __half22float2(*reinterpret_cast<const __half2*>(pb + q));
        int c = c0 + q * 2;
        float s0 = __ldg(g + c) * rsqrtf(__ldg(rv + c) + 1e-5f);
        float s1 = __ldg(g + c + 1) * rsqrtf(__ldg(rv + c + 1) + 1e-5f);
        float t0 = (fa.x + fb.x + __ldg(b + c) - __ldg(rm + c)) * s0 + __ldg(be + c);
        float t1 = (fa.y + fb.y + __ldg(b + c + 1) - __ldg(rm + c + 1)) * s1 + __ldg(be + c + 1);
        __half2 h = __floats2half2_rn(elu1(t0), elu1(t1));
        po[q] = *reinterpret_cast<uint32_t*>(&h);
    }
    reinterpret_cast<uint4*>(Ah)[i] = o;
    uint4 z = make_uint4(0, 0, 0, 0);
    reinterpret_cast<uint4*>(accA)[i] = z;
    reinterpret_cast<uint4*>(accB)[i] = z;
}

// out = ELU(BN3( ELU(BN2(accA+accB + b2)) + acc3 + b3 ))
__global__ void final2_kernel(const __half* __restrict__ accA, const __half* __restrict__ accB,
                              const float* __restrict__ acc3,
                              const float* __restrict__ b2, const float* __restrict__ g2,
                              const float* __restrict__ be2, const float* __restrict__ rm2,
                              const float* __restrict__ rv2,
                              const float* __restrict__ b3, const float* __restrict__ g3,
                              const float* __restrict__ be3, const float* __restrict__ rm3,
                              const float* __restrict__ rv3,
                              float* __restrict__ out) {
    int i = blockIdx.x * blockDim.x + threadIdx.x;
    if (i >= NNODES * 16) return;
    uint4 va = reinterpret_cast<const uint4*>(accA)[i];
    uint4 vb = reinterpret_cast<const uint4*>(accB)[i];
    const uint32_t* pa = reinterpret_cast<const uint32_t*>(&va);
    const uint32_t* pb = reinterpret_cast<const uint32_t*>(&vb);
    float4 s3a = reinterpret_cast<const float4*>(acc3)[i * 2];
    float4 s3b = reinterpret_cast<const float4*>(acc3)[i * 2 + 1];
    float svv[8] = {s3a.x, s3a.y, s3a.z, s3a.w, s3b.x, s3b.y, s3b.z, s3b.w};
    int c0 = (i * 8) & 127;
    float ro[8];
#pragma unroll
    for (int q = 0; q < 4; q++) {
        float2 fa = __half22float2(*reinterpret_cast<const __half2*>(pa + q));
        float2 fb = __half22float2(*reinterpret_cast<const __half2*>(pb + q));
        float acc0 = fa.x + fb.x;
        float acc1 = fa.y + fb.y;
#pragma unroll
        for (int j = 0; j < 2; j++) {
            int c = c0 + q * 2 + j;
            float accv = (j == 0) ? acc0 : acc1;
            float s2 = __ldg(g2 + c) * rsqrtf(__ldg(rv2 + c) + 1e-5f);
            float h = elu1((accv + __ldg(b2 + c) - __ldg(rm2 + c)) * s2 + __ldg(be2 + c));
            float s3 = __ldg(g3 + c) * rsqrtf(__ldg(rv3 + c) + 1e-5f);
            float t = (h + svv[q * 2 + j] + __ldg(b3 + c) - __ldg(rm3 + c)) * s3 + __ldg(be3 + c);
            ro[q * 2 + j] = elu1(t);
        }
    }
    reinterpret_cast<float4*>(out)[i * 2] = make_float4(ro[0], ro[1], ro[2], ro[3]);
    reinterpret_cast<float4*>(out)[i * 2 + 1] = make_float4(ro[4], ro[5], ro[6], ro[7]);
}

// ---------------- launch ----------------
extern "C" void kernel_launch(void* const* d_in, const int* in_sizes, int n_in,
                              void* d_out, int out_size) {
    const float* x   = (const float*)d_in[0];
    const int*   ei  = (const int*)d_in[1];
    const int*   sel = (const int*)d_in[2];
    const float* W1  = (const float*)d_in[3];
    const float* b1  = (const float*)d_in[4];
    const float* g1  = (const float*)d_in[5];
    const float* be1 = (const float*)d_in[6];
    const float* rm1 = (const float*)d_in[7];
    const float* rv1 = (const float*)d_in[8];
    const float* W2  = (const float*)d_in[9];
    const float* b2  = (const float*)d_in[10];
    const float* g2  = (const float*)d_in[11];
    const float* be2 = (const float*)d_in[12];
    const float* rm2 = (const float*)d_in[13];
    const float* rv2 = (const float*)d_in[14];
    const float* W3  = (const float*)d_in[15];
    const float* b3  = (const float*)d_in[16];
    const float* g3  = (const float*)d_in[17];
    const float* be3 = (const float*)d_in[18];
    const float* rm3 = (const float*)d_in[19];
    const float* rv3 = (const float*)d_in[20];
    float* out = (float*)d_out;

    const int E = in_sizes[2];
    const int* src = ei;
    const int* dst = ei + E;

    __half *accA, *accB, *Abx, *Abh, *WbA, *Wb2;
    float* acc3;
    int *cnt, *boffs, *cur, *part;
    uint32_t* ebuf;
    cudaGetSymbolAddress((void**)&accA, g_accA);
    cudaGetSymbolAddress((void**)&accB, g_accB);
    cudaGetSymbolAddress((void**)&acc3, g_acc3);
    cudaGetSymbolAddress((void**)&Abx, g_Abx);
    cudaGetSymbolAddress((void**)&Abh, g_Abh);
    cudaGetSymbolAddress((void**)&WbA, g_WbA);
    cudaGetSymbolAddress((void**)&Wb2, g_Wb2);
    cudaGetSymbolAddress((void**)&cnt, g_cnt);
    cudaGetSymbolAddress((void**)&boffs, g_boffs);
    cudaGetSymbolAddress((void**)&cur, g_cur);
    cudaGetSymbolAddress((void**)&part, g_part);
    cudaGetSymbolAddress((void**)&ebuf, g_ebuf);

    cudaFuncSetAttribute(gemm_scatter_kernel<true>,
                         cudaFuncAttributeMaxDynamicSharedMemorySize, SMEM_BYTES);
    cudaFuncSetAttribute(gemm_scatter_kernel<false>,
                         cudaFuncAttributeMaxDynamicSharedMemorySize, SMEM_BYTES);

    const int ew_blocks = (NNODES * 16 + 255) / 256;
    const int prep_total = 2 * NW + 128 * 128 + NNODES * 32 + NBUCK;
    const int prep_blocks = (prep_total + 255) / 256;
    const int e_blocks = (E + 255) / 256;

    // ---- prep + bucketing (5 launches) ----
    prep_all_kernel<<<prep_blocks, 256>>>(W1, W2, W3, x, WbA, Wb2, Abx, cnt);
    hist_zero_kernel<<<e_blocks, 256>>>(src, sel, cnt, E, accA, accB, acc3);
    scanA_kernel<<<9, 256>>>(cnt, boffs, part);
    scanC_kernel<<<9, 256>>>(boffs, cur, part);
    fill_kernel<<<e_blocks, 256>>>(src, dst, sel, cur, ebuf, E);

    // ---- layer 1 (9-dir -> accA/accB) + shortcut (dir 9 = W3 -> acc3, fp32) ----
    gemm_scatter_kernel<true><<<dim3(NDIR + 1, NTILES), 128, SMEM_BYTES>>>(
        Abx, WbA, boffs, ebuf, accA, accB, acc3);
    bnelu_prep_kernel<<<ew_blocks, 256>>>(accA, accB, b1, g1, be1, rm1, rv1, Abh);

    // ---- layer 2 (9-dir -> accA/accB) ----
    gemm_scatter_kernel<false><<<dim3(NDIR, NTILES), 128, SMEM_BYTES>>>(
        Abh, Wb2, boffs, ebuf, accA, accB, acc3);

    // ---- combine: ELU(BN3(ELU(BN2(accA+accB+b2)) + acc3 + b3)) ----
    final2_kernel<<<ew_blocks, 256>>>(accA, accB, acc3, b2, g2, be2, rm2, rv2,
                                      b3, g3, be3, rm3, rv3, out);
}